// round 6
// baseline (speedup 1.0000x reference)
#include <cuda_runtime.h>
#include <cstdint>
#include <cstddef>

#define NN   8192
#define FIN  256
#define FOUT 128
#define MT   64
#define JT   128
#define SPS  132    // sP row stride (floats): ldmatrix rows -> distinct banks
#define SBTS 132    // sBT row stride
#define NTL  64

__device__ float g_Wh  [NN * FOUT];      // fp32 Wh (for k_score)
__device__ float g_WhrT[FOUT * NN];      // tf32-rounded Wh^T (n-major) for MMA B
__device__ float g_ss[NN], g_us[NN], g_u5[NN];
__device__ float g_sd[NN], g_vd[NN], g_v5[NN];

__device__ __forceinline__ float to_tf32(float x) {
    unsigned r; asm("cvt.rna.tf32.f32 %0, %1;" : "=r"(r) : "f"(x));
    return __uint_as_float(r);
}

#define CPASYNC16(dst, src) \
    asm volatile("cp.async.cg.shared.global [%0], [%1], 16;" :: "r"(dst), "l"(src))
#define CPCOMMIT() asm volatile("cp.async.commit_group;" ::: "memory")
#define CPWAIT0()  asm volatile("cp.async.wait_group 0;" ::: "memory")
#define LDSM4(r0, r1, r2, r3, addr) \
    asm volatile("ldmatrix.sync.aligned.m8n8.x4.shared.b16 {%0,%1,%2,%3}, [%4];" \
                 : "=r"(r0), "=r"(r1), "=r"(r2), "=r"(r3) : "r"(addr))
#define MMA8(d, a0, a1, a2, a3, b0, b1) \
    asm volatile("mma.sync.aligned.m16n8k8.row.col.f32.tf32.tf32.f32 " \
                 "{%0,%1,%2,%3}, {%4,%5,%6,%7}, {%8,%9}, {%0,%1,%2,%3};\n" \
                 : "+f"(d[0]), "+f"(d[1]), "+f"(d[2]), "+f"(d[3]) \
                 : "r"(a0), "r"(a1), "r"(a2), "r"(a3), "r"(b0), "r"(b1))

// ---------------- Phase 1: Wh = h @ W^T (also emits tf32 Wh^T) ----------------
__global__ void __launch_bounds__(256) k_wh(const float* __restrict__ h,
                                            const float* __restrict__ W) {
    __shared__ float sH[32][68];
    __shared__ float sW[32][132];
    const int t = threadIdx.x, i0 = blockIdx.x * 64;
    const int rb = (t >> 5) * 8, cb = (t & 31) * 4;
    float acc[8][4];
#pragma unroll
    for (int r = 0; r < 8; r++)
#pragma unroll
        for (int c = 0; c < 4; c++) acc[r][c] = 0.f;
    for (int k0 = 0; k0 < FIN; k0 += 32) {
        __syncthreads();
#pragma unroll
        for (int it = 0; it < 2; it++) {
            int idx = t + 256 * it, row = idx >> 3, kc = (idx & 7) * 4;
            float4 v = *reinterpret_cast<const float4*>(h + (size_t)(i0 + row) * FIN + k0 + kc);
            sH[kc][row] = v.x; sH[kc + 1][row] = v.y; sH[kc + 2][row] = v.z; sH[kc + 3][row] = v.w;
        }
#pragma unroll
        for (int it = 0; it < 4; it++) {
            int idx = t + 256 * it, f = idx >> 3, kc = (idx & 7) * 4;
            float4 v = *reinterpret_cast<const float4*>(W + (size_t)f * FIN + k0 + kc);
            sW[kc][f] = v.x; sW[kc + 1][f] = v.y; sW[kc + 2][f] = v.z; sW[kc + 3][f] = v.w;
        }
        __syncthreads();
#pragma unroll
        for (int k = 0; k < 32; k++) {
            float a[8], b[4];
            *reinterpret_cast<float4*>(a)     = *reinterpret_cast<const float4*>(&sH[k][rb]);
            *reinterpret_cast<float4*>(a + 4) = *reinterpret_cast<const float4*>(&sH[k][rb + 4]);
            *reinterpret_cast<float4*>(b)     = *reinterpret_cast<const float4*>(&sW[k][cb]);
#pragma unroll
            for (int r = 0; r < 8; r++)
#pragma unroll
                for (int c = 0; c < 4; c++) acc[r][c] = fmaf(a[r], b[c], acc[r][c]);
        }
    }
#pragma unroll
    for (int r = 0; r < 8; r++)
        *reinterpret_cast<float4*>(g_Wh + (size_t)(i0 + rb + r) * FOUT + cb) =
            make_float4(acc[r][0], acc[r][1], acc[r][2], acc[r][3]);
    // transposed tf32 copy: g_WhrT[n][j], j = i0+rb..rb+7 contiguous
#pragma unroll
    for (int c = 0; c < 4; c++) {
        float4 v0 = make_float4(to_tf32(acc[0][c]), to_tf32(acc[1][c]),
                                to_tf32(acc[2][c]), to_tf32(acc[3][c]));
        float4 v1 = make_float4(to_tf32(acc[4][c]), to_tf32(acc[5][c]),
                                to_tf32(acc[6][c]), to_tf32(acc[7][c]));
        float* dst = g_WhrT + (size_t)(cb + c) * NN + i0 + rb;
        *reinterpret_cast<float4*>(dst)     = v0;
        *reinterpret_cast<float4*>(dst + 4) = v1;
    }
}

// ---------------- Phase 2: scores + exp factors ----------------
__global__ void __launch_bounds__(256) k_score(const float* __restrict__ a_vec) {
    int gw = (blockIdx.x * blockDim.x + threadIdx.x) >> 5, lane = threadIdx.x & 31;
    if (gw >= NN) return;
    float4 w  = reinterpret_cast<const float4*>(g_Wh + (size_t)gw * FOUT)[lane];
    float4 as = reinterpret_cast<const float4*>(a_vec)[lane];
    float4 ad = reinterpret_cast<const float4*>(a_vec + FOUT)[lane];
    float ss = w.x * as.x + w.y * as.y + w.z * as.z + w.w * as.w;
    float sd = w.x * ad.x + w.y * ad.y + w.z * ad.z + w.w * ad.w;
#pragma unroll
    for (int o = 16; o > 0; o >>= 1) {
        ss += __shfl_xor_sync(0xffffffffu, ss, o);
        sd += __shfl_xor_sync(0xffffffffu, sd, o);
    }
    if (lane == 0) {
        g_ss[gw] = ss; g_us[gw] = expf(ss); g_u5[gw] = expf(0.2f * ss);
        g_sd[gw] = sd; g_vd[gw] = expf(sd); g_v5[gw] = expf(0.2f * sd);
    }
}

// ------- Phase 3: fused masked-softmax @ Wh (ldmatrix + tf32 mma.sync) -------
extern __shared__ float dynsmem[];

__global__ void __launch_bounds__(256, 1) k_gat(const int* __restrict__ adj,
                                                float* __restrict__ out) {
    float* sP[2];
    float* sB[2];
    sP[0] = dynsmem;
    sP[1] = sP[0] + MT * SPS;
    sB[0] = sP[1] + MT * SPS;
    sB[1] = sB[0] + FOUT * SBTS;
    float* sDen = sB[1] + FOUT * SBTS;

    const int t    = threadIdx.x;
    const int lane = t & 31;
    const int w    = t >> 5;
    const int i0   = blockIdx.x * MT;
    const int jl   = lane * 4;

    const uint32_t sPu[2] = {(uint32_t)__cvta_generic_to_shared(sP[0]),
                             (uint32_t)__cvta_generic_to_shared(sP[1])};
    const uint32_t sBu[2] = {(uint32_t)__cvta_generic_to_shared(sB[0]),
                             (uint32_t)__cvta_generic_to_shared(sB[1])};

    // warp tile: 32 rows x 32 cols
    const int mrow = (w & 1) * 32;
    const int ncol = (w >> 1) * 32;
    const int qr   = lane >> 2;
    const int qc   = lane & 3;
    const int g    = lane >> 3;      // ldmatrix matrix id
    const int lr   = lane & 7;       // ldmatrix row in matrix
    const uint32_t aoffs = (uint32_t)(((mrow + (g & 1) * 8 + lr) * SPS + (g >> 1) * 4) * 4);
    const uint32_t boffs = (uint32_t)(((ncol + (g >> 1) * 8 + lr) * SBTS + (g & 1) * 4) * 4);

    // row-side constants (P-gen rows w + 8*it)
    float ssr[8], usr[8], u5r[8], den[8];
#pragma unroll
    for (int it = 0; it < 8; it++) {
        int gr = i0 + w + 8 * it;
        ssr[it] = g_ss[gr]; usr[it] = g_us[gr]; u5r[it] = g_u5[gr];
        den[it] = 0.f;
    }

    float acc[2][4][4];
#pragma unroll
    for (int mb = 0; mb < 2; mb++)
#pragma unroll
        for (int nt = 0; nt < 4; nt++)
#pragma unroll
            for (int c = 0; c < 4; c++) acc[mb][nt][c] = 0.f;

    // ---- prologue ----
    int4   amC[8];
    float4 sdC, vdC, v5C;
    sdC = *reinterpret_cast<const float4*>(g_sd + jl);
    vdC = *reinterpret_cast<const float4*>(g_vd + jl);
    v5C = *reinterpret_cast<const float4*>(g_v5 + jl);
#pragma unroll
    for (int it = 0; it < 8; it++)
        amC[it] = *reinterpret_cast<const int4*>(adj + (size_t)(i0 + w + 8 * it) * NN + jl);

    // P-gen(0) -> sP[0]
#pragma unroll
    for (int it = 0; it < 8; it++) {
        int r = w + 8 * it;
        float p0 = (ssr[it] + sdC.x) > 0.f ? usr[it] * vdC.x : u5r[it] * v5C.x;
        float p1 = (ssr[it] + sdC.y) > 0.f ? usr[it] * vdC.y : u5r[it] * v5C.y;
        float p2 = (ssr[it] + sdC.z) > 0.f ? usr[it] * vdC.z : u5r[it] * v5C.z;
        float p3 = (ssr[it] + sdC.w) > 0.f ? usr[it] * vdC.w : u5r[it] * v5C.w;
        p0 = amC[it].x > 0 ? p0 : 0.f;  p1 = amC[it].y > 0 ? p1 : 0.f;
        p2 = amC[it].z > 0 ? p2 : 0.f;  p3 = amC[it].w > 0 ? p3 : 0.f;
        den[it] += (p0 + p1) + (p2 + p3);
        *reinterpret_cast<float4*>(&sP[0][r * SPS + jl]) =
            make_float4(to_tf32(p0), to_tf32(p1), to_tf32(p2), to_tf32(p3));
    }
    // cp.async B(0)
#pragma unroll
    for (int i = 0; i < 16; i++) {
        int c = t + 256 * i, n = c >> 5, k4 = (c & 31) * 4;
        CPASYNC16(sBu[0] + (uint32_t)(n * SBTS + k4) * 4u, g_WhrT + (size_t)n * NN + k4);
    }
    CPCOMMIT();
    // regs for tile 1
    sdC = *reinterpret_cast<const float4*>(g_sd + JT + jl);
    vdC = *reinterpret_cast<const float4*>(g_vd + JT + jl);
    v5C = *reinterpret_cast<const float4*>(g_v5 + JT + jl);
#pragma unroll
    for (int it = 0; it < 8; it++)
        amC[it] = *reinterpret_cast<const int4*>(adj + (size_t)(i0 + w + 8 * it) * NN + JT + jl);
    CPWAIT0();
    __syncthreads();

#pragma unroll 1
    for (int jt = 0; jt < NTL; jt++) {
        const int s = jt & 1;
        // --- issue cp.async for B(jt+1) ---
        if (jt + 1 < NTL) {
            const float* bsrc = g_WhrT + (size_t)(jt + 1) * JT;
            const uint32_t sBn = sBu[s ^ 1];
#pragma unroll
            for (int i = 0; i < 16; i++) {
                int c = t + 256 * i, n = c >> 5, k4 = (c & 31) * 4;
                CPASYNC16(sBn + (uint32_t)(n * SBTS + k4) * 4u, bsrc + (size_t)n * NN + k4);
            }
        }
        CPCOMMIT();

        // --- P-gen(jt+1) -> sP[s^1] ---
        if (jt + 1 < NTL) {
#pragma unroll
            for (int it = 0; it < 8; it++) {
                int r = w + 8 * it;
                float p0 = (ssr[it] + sdC.x) > 0.f ? usr[it] * vdC.x : u5r[it] * v5C.x;
                float p1 = (ssr[it] + sdC.y) > 0.f ? usr[it] * vdC.y : u5r[it] * v5C.y;
                float p2 = (ssr[it] + sdC.z) > 0.f ? usr[it] * vdC.z : u5r[it] * v5C.z;
                float p3 = (ssr[it] + sdC.w) > 0.f ? usr[it] * vdC.w : u5r[it] * v5C.w;
                p0 = amC[it].x > 0 ? p0 : 0.f;  p1 = amC[it].y > 0 ? p1 : 0.f;
                p2 = amC[it].z > 0 ? p2 : 0.f;  p3 = amC[it].w > 0 ? p3 : 0.f;
                den[it] += (p0 + p1) + (p2 + p3);
                *reinterpret_cast<float4*>(&sP[s ^ 1][r * SPS + jl]) =
                    make_float4(to_tf32(p0), to_tf32(p1), to_tf32(p2), to_tf32(p3));
            }
        }
        // --- prefetch regs for tile jt+2 ---
        if (jt + 2 < NTL) {
            const int j0n = (jt + 2) * JT;
            sdC = *reinterpret_cast<const float4*>(g_sd + j0n + jl);
            vdC = *reinterpret_cast<const float4*>(g_vd + j0n + jl);
            v5C = *reinterpret_cast<const float4*>(g_v5 + j0n + jl);
#pragma unroll
            for (int it = 0; it < 8; it++)
                amC[it] = *reinterpret_cast<const int4*>(adj + (size_t)(i0 + w + 8 * it) * NN + j0n + jl);
        }

        // --- MMA(jt): ldmatrix operands, 8 mma per k-step ---
        const uint32_t pA = sPu[s] + aoffs;
        const uint32_t pB = sBu[s] + boffs;
#pragma unroll
        for (int ks = 0; ks < 16; ks++) {
            unsigned a0[4], a1[4], b0[4], b1[4];
            LDSM4(a0[0], a0[1], a0[2], a0[3], pA + ks * 32);
            LDSM4(a1[0], a1[1], a1[2], a1[3], pA + 16 * SPS * 4 + ks * 32);
            LDSM4(b0[0], b0[1], b0[2], b0[3], pB + ks * 32);
            LDSM4(b1[0], b1[1], b1[2], b1[3], pB + 16 * SBTS * 4 + ks * 32);
            MMA8(acc[0][0], a0[0], a0[1], a0[2], a0[3], b0[0], b0[1]);
            MMA8(acc[0][1], a0[0], a0[1], a0[2], a0[3], b0[2], b0[3]);
            MMA8(acc[0][2], a0[0], a0[1], a0[2], a0[3], b1[0], b1[1]);
            MMA8(acc[0][3], a0[0], a0[1], a0[2], a0[3], b1[2], b1[3]);
            MMA8(acc[1][0], a1[0], a1[1], a1[2], a1[3], b0[0], b0[1]);
            MMA8(acc[1][1], a1[0], a1[1], a1[2], a1[3], b0[2], b0[3]);
            MMA8(acc[1][2], a1[0], a1[1], a1[2], a1[3], b1[0], b1[1]);
            MMA8(acc[1][3], a1[0], a1[1], a1[2], a1[3], b1[2], b1[3]);
        }
        CPWAIT0();
        __syncthreads();
    }

    // ---- epilogue ----
#pragma unroll
    for (int it = 0; it < 8; it++) {
        float d = den[it];
#pragma unroll
        for (int o = 16; o > 0; o >>= 1) d += __shfl_xor_sync(0xffffffffu, d, o);
        if (lane == 0) sDen[w + 8 * it] = d;
    }
    __syncthreads();

#pragma unroll
    for (int mb = 0; mb < 2; mb++) {
        const int rbase = mrow + mb * 16 + qr;
        const float rd0 = 1.f / sDen[rbase];
        const float rd1 = 1.f / sDen[rbase + 8];
        const int r0 = i0 + rbase;
#pragma unroll
        for (int nt = 0; nt < 4; nt++) {
            int col = ncol + nt * 8 + qc * 2;
            *reinterpret_cast<float2*>(out + (size_t)r0 * FOUT + col) =
                make_float2(acc[mb][nt][0] * rd0, acc[mb][nt][1] * rd0);
            *reinterpret_cast<float2*>(out + (size_t)(r0 + 8) * FOUT + col) =
                make_float2(acc[mb][nt][2] * rd1, acc[mb][nt][3] * rd1);
        }
    }
}

// ---------------------------------------------------------------
extern "C" void kernel_launch(void* const* d_in, const int* in_sizes, int n_in,
                              void* d_out, int out_size) {
    const float* h   = (const float*)d_in[0];
    const int*   adj = (const int*)d_in[1];
    const float* W   = (const float*)d_in[2];
    const float* a   = (const float*)d_in[3];
    float*       out = (float*)d_out;
    (void)in_sizes; (void)n_in; (void)out_size;

    const int smem_bytes = (2 * MT * SPS + 2 * FOUT * SBTS + MT) * (int)sizeof(float);
    static int inited = 0;
    if (!inited) {
        cudaFuncSetAttribute(k_gat, cudaFuncAttributeMaxDynamicSharedMemorySize, smem_bytes);
        inited = 1;
    }
    k_wh<<<NN / 64, 256>>>(h, W);
    k_score<<<NN / 8, 256>>>(a);
    k_gat<<<NN / MT, 256, smem_bytes>>>(adj, out);
}